// round 3
// baseline (speedup 1.0000x reference)
#include <cuda_runtime.h>
#include <math.h>

// ---------------------------------------------------------------------------
// SelfAttention2d: x(16,256,32,32) fp32
//   y = GroupNorm32(x) ; qkv = Wqkv @ y + bqkv ; attention(4 heads, hd=64)
//   out = x + Wproj @ attnout + bproj
// Layouts: everything kept channel-major [b][c][s], s = h*32+w (contiguous).
// ---------------------------------------------------------------------------

#define BATCH 16
#define CH    256
#define SEQ   1024
#define HEADS 4
#define HD    64
#define GROUPS 32
#define CPG   (CH / GROUPS)        // 8
#define GN_ELEMS (CPG * SEQ)       // 8192 contiguous floats per (b,g)

// Scratch (static device memory — allocation-free per harness rules)
__device__ float g_y   [BATCH * CH     * SEQ];   // groupnorm output
__device__ float g_qkv [BATCH * 3 * CH * SEQ];   // qkv projections
__device__ float g_att [BATCH * CH     * SEQ];   // attention output

// ---------------------------------------------------------------------------
// Kernel 1: GroupNorm. One block per (b,g) = 512 blocks, 256 threads.
// Each group is one contiguous 8192-float chunk.
// ---------------------------------------------------------------------------
__global__ __launch_bounds__(256)
void gn_kernel(const float* __restrict__ x,
               const float* __restrict__ gw,
               const float* __restrict__ gb,
               float* __restrict__ y)
{
    const int bg  = blockIdx.x;            // b*32 + g
    const int tid = threadIdx.x;
    const float4* __restrict__ xp = (const float4*)(x + (size_t)bg * GN_ELEMS);
    float4* __restrict__ yp = (float4*)(y + (size_t)bg * GN_ELEMS);

    float s = 0.f, ss = 0.f;
    float4 v[8];
#pragma unroll
    for (int r = 0; r < 8; r++) {
        v[r] = xp[tid + r * 256];
        s  += v[r].x + v[r].y + v[r].z + v[r].w;
        ss += v[r].x*v[r].x + v[r].y*v[r].y + v[r].z*v[r].z + v[r].w*v[r].w;
    }

    __shared__ float s1[256], s2[256];
    s1[tid] = s; s2[tid] = ss;
    __syncthreads();
    for (int st = 128; st > 0; st >>= 1) {
        if (tid < st) { s1[tid] += s1[tid + st]; s2[tid] += s2[tid + st]; }
        __syncthreads();
    }
    const float mean = s1[0] * (1.0f / GN_ELEMS);
    const float var  = s2[0] * (1.0f / GN_ELEMS) - mean * mean;
    const float inv  = rsqrtf(var + 1e-5f);
    const int g = bg & (GROUPS - 1);

#pragma unroll
    for (int r = 0; r < 8; r++) {
        int idx = (tid + r * 256) * 4;           // element index in chunk
        int c = g * CPG + (idx >> 10);           // channel (same for all 4 lanes)
        float wsc = gw[c] * inv;
        float bia = gb[c] - mean * wsc;
        float4 o;
        o.x = v[r].x * wsc + bia;
        o.y = v[r].y * wsc + bia;
        o.z = v[r].z * wsc + bia;
        o.w = v[r].w * wsc + bia;
        yp[tid + r * 256] = o;
    }
}

// ---------------------------------------------------------------------------
// Kernel 2/4: batched SGEMM  C[b] = W(MxK) @ X[b](KxN) + bias (+ residual)
// K=256, N=1024 fixed. 64x64x16 tiles, 256 threads, 4x4 microtiles.
// grid = (N/64, M/64, BATCH)
// ---------------------------------------------------------------------------
template <bool RESIDUAL>
__global__ __launch_bounds__(256)
void gemm_kernel(const float* __restrict__ W,
                 const float* __restrict__ bias,
                 const float* __restrict__ X,
                 const float* __restrict__ res,
                 float* __restrict__ out,
                 int M)
{
    __shared__ float As[16][64];
    __shared__ float Bs[16][64];

    const int tid = threadIdx.x;
    const int tx = tid & 15;       // n microtile
    const int ty = tid >> 4;       // m microtile
    const int bx = blockIdx.x;     // n tile
    const int by = blockIdx.y;     // m tile
    const int bz = blockIdx.z;     // batch

    const float* __restrict__ Wb = W + (size_t)by * 64 * 256;
    const float* __restrict__ Xb = X + (size_t)bz * 256 * SEQ + bx * 64;

    float acc[4][4] = {};

    const int ar = tid >> 2, ac = (tid & 3) * 4;     // A-load coords
    const int br = tid >> 4, bc = (tid & 15) * 4;    // B-load coords

    for (int k0 = 0; k0 < 256; k0 += 16) {
        float4 a = *(const float4*)&Wb[ar * 256 + k0 + ac];
        As[ac + 0][ar] = a.x; As[ac + 1][ar] = a.y;
        As[ac + 2][ar] = a.z; As[ac + 3][ar] = a.w;
        *(float4*)&Bs[br][bc] = *(const float4*)&Xb[(size_t)(k0 + br) * SEQ + bc];
        __syncthreads();

#pragma unroll
        for (int k = 0; k < 16; k++) {
            float4 av = *(const float4*)&As[k][ty * 4];
            float4 bv = *(const float4*)&Bs[k][tx * 4];
            float aa[4] = {av.x, av.y, av.z, av.w};
            float bb[4] = {bv.x, bv.y, bv.z, bv.w};
#pragma unroll
            for (int i = 0; i < 4; i++)
#pragma unroll
                for (int j = 0; j < 4; j++)
                    acc[i][j] = fmaf(aa[i], bb[j], acc[i][j]);
        }
        __syncthreads();
    }

#pragma unroll
    for (int i = 0; i < 4; i++) {
        const int m = by * 64 + ty * 4 + i;
        const float bv = bias[m];
        const size_t o = (size_t)bz * M * SEQ + (size_t)m * SEQ + bx * 64 + tx * 4;
        float4 r;
        r.x = acc[i][0] + bv; r.y = acc[i][1] + bv;
        r.z = acc[i][2] + bv; r.w = acc[i][3] + bv;
        if (RESIDUAL) {
            float4 rv = *(const float4*)&res[o];
            r.x += rv.x; r.y += rv.y; r.z += rv.z; r.w += rv.w;
        }
        *(float4*)&out[o] = r;
    }
}

// ---------------------------------------------------------------------------
// Kernel 3: fused flash attention, fp32.
// grid = (SEQ/64 i-tiles, HEADS, BATCH), 256 threads.
// Thread (i4 = tid>>4, c4 = tid&15): scores microtile 4i x 4j, PV microtile
// 4i x 4d. Row stats reduced over the 16-lane group sharing i4 via shfl_xor.
// Dynamic smem: qs[64][64] ks[64][64] vs[64][68] ps[64][68]  (67.6 KB)
// ---------------------------------------------------------------------------
#define VP 68   // padded row length for vs / ps

__global__ __launch_bounds__(256)
void attn_kernel(const float* __restrict__ qkv, float* __restrict__ att)
{
    extern __shared__ float sm[];
    float* qs = sm;                 // [64][64]  q (pre-scaled), [d][i]
    float* ks = sm + 4096;          // [64][64]  k tile, [d][j]
    float* vs = sm + 8192;          // [64][VP]  v tile, [d][j]
    float* ps = sm + 8192 + 64*VP;  // [64][VP]  probs, [i][j]

    const int tid = threadIdx.x;
    const int i4 = tid >> 4;
    const int c4 = tid & 15;
    const int i0 = blockIdx.x * 64;
    const int h  = blockIdx.y;
    const int b  = blockIdx.z;

    const size_t base = ((size_t)b * 3 * CH + h * HD) * SEQ;
    const float* __restrict__ qg = qkv + base;                       // q channels
    const float* __restrict__ kg = qkv + base + (size_t)CH * SEQ;    // k channels
    const float* __restrict__ vg = qkv + base + (size_t)2 * CH * SEQ;

    const float scale = 0.125f;  // hd^-0.5

    // load q tile (scaled): 64 d-rows x 64 i
#pragma unroll
    for (int r = 0; r < 4; r++) {
        int lin = (tid + r * 256) * 4;
        int d = lin >> 6, i = lin & 63;
        float4 v = *(const float4*)&qg[(size_t)d * SEQ + i0 + i];
        v.x *= scale; v.y *= scale; v.z *= scale; v.w *= scale;
        *(float4*)&qs[d * 64 + i] = v;
    }

    float m[4], l[4], acc[4][4];
#pragma unroll
    for (int i = 0; i < 4; i++) {
        m[i] = -1e30f; l[i] = 0.f;
#pragma unroll
        for (int j = 0; j < 4; j++) acc[i][j] = 0.f;
    }

    const float4* qs4 = (const float4*)qs;
    const float4* ks4 = (const float4*)ks;

    for (int jt = 0; jt < SEQ / 64; jt++) {
        const int j0 = jt * 64;
        __syncthreads();   // protect ks/vs/ps from previous iteration consumers
#pragma unroll
        for (int r = 0; r < 4; r++) {
            int lin = (tid + r * 256) * 4;
            int d = lin >> 6, j = lin & 63;
            *(float4*)&ks[d * 64 + j] =
                *(const float4*)&kg[(size_t)d * SEQ + j0 + j];
            *(float4*)&vs[d * VP + j] =
                *(const float4*)&vg[(size_t)d * SEQ + j0 + j];
        }
        __syncthreads();

        // scores: sc[ii][jj] = q[:, i4*4+ii] . k[:, c4*4+jj]   (q pre-scaled)
        float sc[4][4] = {};
#pragma unroll 8
        for (int d = 0; d < 64; d++) {
            float4 qv = qs4[d * 16 + i4];
            float4 kv = ks4[d * 16 + c4];
            float qa[4] = {qv.x, qv.y, qv.z, qv.w};
            float ka[4] = {kv.x, kv.y, kv.z, kv.w};
#pragma unroll
            for (int ii = 0; ii < 4; ii++)
#pragma unroll
                for (int jj = 0; jj < 4; jj++)
                    sc[ii][jj] = fmaf(qa[ii], ka[jj], sc[ii][jj]);
        }

        // online softmax per row (16-lane group reduction)
#pragma unroll
        for (int ii = 0; ii < 4; ii++) {
            float rm = fmaxf(fmaxf(sc[ii][0], sc[ii][1]),
                             fmaxf(sc[ii][2], sc[ii][3]));
            rm = fmaxf(rm, __shfl_xor_sync(0xffffffffu, rm, 1));
            rm = fmaxf(rm, __shfl_xor_sync(0xffffffffu, rm, 2));
            rm = fmaxf(rm, __shfl_xor_sync(0xffffffffu, rm, 4));
            rm = fmaxf(rm, __shfl_xor_sync(0xffffffffu, rm, 8));
            float nm = fmaxf(m[ii], rm);
            float corr = __expf(m[ii] - nm);
            float rs = 0.f;
#pragma unroll
            for (int jj = 0; jj < 4; jj++) {
                float p = __expf(sc[ii][jj] - nm);
                sc[ii][jj] = p;
                rs += p;
            }
            rs += __shfl_xor_sync(0xffffffffu, rs, 1);
            rs += __shfl_xor_sync(0xffffffffu, rs, 2);
            rs += __shfl_xor_sync(0xffffffffu, rs, 4);
            rs += __shfl_xor_sync(0xffffffffu, rs, 8);
            l[ii] = l[ii] * corr + rs;
            m[ii] = nm;
#pragma unroll
            for (int dd = 0; dd < 4; dd++) acc[ii][dd] *= corr;
        }

        // stage probs to smem for the PV stage
#pragma unroll
        for (int ii = 0; ii < 4; ii++)
            *(float4*)&ps[(i4 * 4 + ii) * VP + c4 * 4] =
                make_float4(sc[ii][0], sc[ii][1], sc[ii][2], sc[ii][3]);
        __syncthreads();

        // PV: acc[ii][dd] += sum_j p[i][j] * v[d][j]   (c4 now indexes d)
#pragma unroll 4
        for (int j = 0; j < 64; j += 4) {
            float4 pv[4], vv[4];
#pragma unroll
            for (int ii = 0; ii < 4; ii++)
                pv[ii] = *(const float4*)&ps[(i4 * 4 + ii) * VP + j];
#pragma unroll
            for (int dd = 0; dd < 4; dd++)
                vv[dd] = *(const float4*)&vs[(c4 * 4 + dd) * VP + j];
#pragma unroll
            for (int ii = 0; ii < 4; ii++)
#pragma unroll
                for (int dd = 0; dd < 4; dd++)
                    acc[ii][dd] += pv[ii].x * vv[dd].x + pv[ii].y * vv[dd].y
                                 + pv[ii].z * vv[dd].z + pv[ii].w * vv[dd].w;
        }
    }

    // write attnout[b][h*64 + d][i0 + i]
    float* __restrict__ og = att + ((size_t)b * CH + h * HD) * SEQ + i0;
#pragma unroll
    for (int ii = 0; ii < 4; ii++) {
        const float inv = 1.0f / l[ii];
#pragma unroll
        for (int dd = 0; dd < 4; dd++)
            og[(size_t)(c4 * 4 + dd) * SEQ + i4 * 4 + ii] = acc[ii][dd] * inv;
    }
}

// ---------------------------------------------------------------------------
extern "C" void kernel_launch(void* const* d_in, const int* in_sizes, int n_in,
                              void* d_out, int out_size)
{
    const float* x      = (const float*)d_in[0];
    const float* gn_w   = (const float*)d_in[1];
    const float* gn_b   = (const float*)d_in[2];
    const float* qkv_w  = (const float*)d_in[3];
    const float* qkv_b  = (const float*)d_in[4];
    const float* proj_w = (const float*)d_in[5];
    const float* proj_b = (const float*)d_in[6];
    float* out = (float*)d_out;

    float *y, *qkv, *att;
    cudaGetSymbolAddress((void**)&y,   g_y);
    cudaGetSymbolAddress((void**)&qkv, g_qkv);
    cudaGetSymbolAddress((void**)&att, g_att);

    const int attn_smem = (8192 + 2 * 64 * VP) * (int)sizeof(float);  // 67.6 KB
    cudaFuncSetAttribute(attn_kernel,
                         cudaFuncAttributeMaxDynamicSharedMemorySize, attn_smem);

    // 1. GroupNorm
    gn_kernel<<<BATCH * GROUPS, 256>>>(x, gn_w, gn_b, y);

    // 2. QKV projection: (768x256) @ (256x1024) per batch
    gemm_kernel<false><<<dim3(SEQ / 64, 3 * CH / 64, BATCH), 256>>>(
        qkv_w, qkv_b, y, nullptr, qkv, 3 * CH);

    // 3. fused attention
    attn_kernel<<<dim3(SEQ / 64, HEADS, BATCH), 256, attn_smem>>>(qkv, att);

    // 4. output projection + bias + residual
    gemm_kernel<true><<<dim3(SEQ / 64, CH / 64, BATCH), 256>>>(
        proj_w, proj_b, att, x, out, CH);
}

// round 5
// speedup vs baseline: 3.0769x; 3.0769x over previous
#include <cuda_runtime.h>
#include <cuda_bf16.h>
#include <math.h>
#include <cstdint>

// ---------------------------------------------------------------------------
// SelfAttention2d via warp-level mma.sync (bf16 split hi/lo, fp32 accum).
// tcgen05 is unavailable: harness compiles PTX for compute_103 (no 'a'),
// which gates out all tcgen05/TMEM instructions. mma.sync m16n8k16 bf16 is
// plain sm_80+ PTX and runs on the tensor pipe.
// ---------------------------------------------------------------------------

#define BATCH 16
#define CH    256
#define SEQ   1024
#define HEADS 4
#define GROUPS 32
#define CPG   8
#define GN_ELEMS 8192

typedef __nv_bfloat16 bf16;

// --------------------------- scratch (static) -------------------------------
__device__ __align__(256) bf16 g_qh[BATCH * 3 * CH * SEQ];  // qkv hi [b][768][s]
__device__ __align__(256) bf16 g_ql[BATCH * 3 * CH * SEQ];
__device__ __align__(256) bf16 g_yh[BATCH * SEQ * CH];      // gn out [b][s][c]
__device__ __align__(256) bf16 g_yl[BATCH * SEQ * CH];
__device__ __align__(256) bf16 g_ah[BATCH * SEQ * CH];      // attn out [b][s][c]
__device__ __align__(256) bf16 g_al[BATCH * SEQ * CH];
__device__ __align__(256) bf16 g_wqh[3 * CH * CH];
__device__ __align__(256) bf16 g_wql[3 * CH * CH];
__device__ __align__(256) bf16 g_wph[CH * CH];
__device__ __align__(256) bf16 g_wpl[CH * CH];

// --------------------------- helpers ----------------------------------------
__device__ __forceinline__ uint32_t smem_u32(const void* p) {
    uint32_t a;
    asm("{ .reg .u64 t; cvta.to.shared.u64 t, %1; cvt.u32.u64 %0, t; }"
        : "=r"(a) : "l"(p));
    return a;
}

#define LDSM4(R, A)                                                          \
    asm volatile("ldmatrix.sync.aligned.m8n8.x4.shared.b16 {%0,%1,%2,%3},[%4];" \
        : "=r"((R)[0]), "=r"((R)[1]), "=r"((R)[2]), "=r"((R)[3]) : "r"(A))
#define LDSM4T(R, A)                                                         \
    asm volatile("ldmatrix.sync.aligned.m8n8.x4.trans.shared.b16 {%0,%1,%2,%3},[%4];" \
        : "=r"((R)[0]), "=r"((R)[1]), "=r"((R)[2]), "=r"((R)[3]) : "r"(A))

__device__ __forceinline__ void mma16816(float* d, const uint32_t* a,
                                         const uint32_t* b) {
    asm volatile(
        "mma.sync.aligned.m16n8k16.row.col.f32.bf16.bf16.f32 "
        "{%0,%1,%2,%3}, {%4,%5,%6,%7}, {%8,%9}, {%0,%1,%2,%3};"
        : "+f"(d[0]), "+f"(d[1]), "+f"(d[2]), "+f"(d[3])
        : "r"(a[0]), "r"(a[1]), "r"(a[2]), "r"(a[3]), "r"(b[0]), "r"(b[1]));
}

// pack two floats -> bf16x2 word (a at lower address)
__device__ __forceinline__ uint32_t pk2(float a, float b) {
    bf16 x = __float2bfloat16(a), y = __float2bfloat16(b);
    return (uint32_t)*(unsigned short*)&x | ((uint32_t)*(unsigned short*)&y << 16);
}
__device__ __forceinline__ void split2(float v, float& h, float& l) {
    bf16 hb = __float2bfloat16(v);
    h = __bfloat162float(hb);
    l = v - h;
}

// ---------------------------------------------------------------------------
// Kernel 0: fp32 -> (hi, lo) bf16 split of weights
// ---------------------------------------------------------------------------
__global__ void split_kernel(const float* __restrict__ w,
                             bf16* __restrict__ hi, bf16* __restrict__ lo, int n)
{
    int i = blockIdx.x * blockDim.x + threadIdx.x;
    if (i < n) {
        float v = w[i], h, l;
        split2(v, h, l);
        hi[i] = __float2bfloat16(h);
        lo[i] = __float2bfloat16(l);
    }
}

// ---------------------------------------------------------------------------
// Kernel 1: GroupNorm -> split-bf16 planes [b][s][c]. One block per (b,g).
// ---------------------------------------------------------------------------
#define BUFP 1028

__global__ __launch_bounds__(256)
void gn_kernel(const float* __restrict__ x,
               const float* __restrict__ gw,
               const float* __restrict__ gb,
               bf16* __restrict__ yh, bf16* __restrict__ yl)
{
    __shared__ float s1[256], s2[256];
    __shared__ float buf[CPG * BUFP];

    const int bg  = blockIdx.x;
    const int b   = bg >> 5;
    const int g   = bg & 31;
    const int tid = threadIdx.x;
    const float4* __restrict__ xp = (const float4*)(x + (size_t)bg * GN_ELEMS);

    float s = 0.f, ss = 0.f;
#pragma unroll
    for (int r = 0; r < 8; r++) {
        float4 v = xp[tid + r * 256];
        s  += v.x + v.y + v.z + v.w;
        ss += v.x*v.x + v.y*v.y + v.z*v.z + v.w*v.w;
        *(float4*)&buf[r * BUFP + tid * 4] = v;
    }
    s1[tid] = s; s2[tid] = ss;
    __syncthreads();
    for (int st = 128; st > 0; st >>= 1) {
        if (tid < st) { s1[tid] += s1[tid + st]; s2[tid] += s2[tid + st]; }
        __syncthreads();
    }
    const float mean = s1[0] * (1.0f / GN_ELEMS);
    const float var  = s2[0] * (1.0f / GN_ELEMS) - mean * mean;
    const float inv  = rsqrtf(var + 1e-5f);

    float wsc[CPG], bia[CPG];
#pragma unroll
    for (int cc = 0; cc < CPG; cc++) {
        wsc[cc] = gw[g * CPG + cc] * inv;
        bia[cc] = gb[g * CPG + cc] - mean * wsc[cc];
    }

    union { uint32_t u[4]; uint4 v; } ph, pl;
#pragma unroll
    for (int q = 0; q < 4; q++) {
        int sp = tid + q * 256;
        size_t o = ((size_t)b * SEQ + sp) * CH + g * CPG;
#pragma unroll
        for (int p2 = 0; p2 < 4; p2++) {
            float v0 = buf[(p2*2    ) * BUFP + sp] * wsc[p2*2    ] + bia[p2*2    ];
            float v1 = buf[(p2*2 + 1) * BUFP + sp] * wsc[p2*2 + 1] + bia[p2*2 + 1];
            float h0, l0, h1, l1;
            split2(v0, h0, l0); split2(v1, h1, l1);
            ph.u[p2] = pk2(h0, h1);
            pl.u[p2] = pk2(l0, l1);
        }
        *(uint4*)&yh[o] = ph.v;
        *(uint4*)&yl[o] = pl.v;
    }
}

// ---------------------------------------------------------------------------
// Kernel 2/4: split-bf16 mma GEMM.  D[m][n] = sum_k A[m][k] * B[n][k]
// A = weights [M][256] hi/lo ; B = activations [b][n][256] hi/lo.
// Block 128m x 128n, 8 warps (2m x 4n), warp 64x32, k-chunks of 32.
// MODE 0: qkv — write split bf16 planes [b][m][SEQ], q rows scaled by 0.125.
// MODE 1: proj — write fp32 out [b][m][SEQ] + bias + residual.
// ---------------------------------------------------------------------------
#define PADK 40

template <int MODE>
__global__ __launch_bounds__(256)
void mma_gemm(const bf16* __restrict__ Ah, const bf16* __restrict__ Al,
              const bf16* __restrict__ Bh, const bf16* __restrict__ Bl,
              const float* __restrict__ bias, const float* __restrict__ resid,
              bf16* __restrict__ Oh, bf16* __restrict__ Ol,
              float* __restrict__ outf)
{
    __shared__ __align__(16) unsigned short sAh[128 * PADK], sAl[128 * PADK];
    __shared__ __align__(16) unsigned short sBh[128 * PADK], sBl[128 * PADK];

    const int tid = threadIdx.x, lane = tid & 31, w = tid >> 5;
    const int wm = w >> 2, wn = w & 3;
    const int bx = blockIdx.x, by = blockIdx.y, bz = blockIdx.z;

    const size_t abase = (size_t)by * 128 * 256;
    const size_t bbase = ((size_t)bz * SEQ + bx * 128) * 256;

    const uint32_t uAh = smem_u32(sAh), uAl = smem_u32(sAl);
    const uint32_t uBh = smem_u32(sBh), uBl = smem_u32(sBl);

    float acc[4][4][4] = {};
    const int r = lane & 7, g = lane >> 3;

    for (int kc = 0; kc < 8; kc++) {
        const int k0 = kc * 32;
#pragma unroll
        for (int rr = 0; rr < 2; rr++) {
            int lin = tid * 8 + rr * 2048;
            int row = lin >> 5, col = lin & 31;
            size_t ga = abase + (size_t)row * 256 + k0 + col;
            size_t gbp = bbase + (size_t)row * 256 + k0 + col;
            *(uint4*)&sAh[row * PADK + col] = *(const uint4*)(Ah + ga);
            *(uint4*)&sAl[row * PADK + col] = *(const uint4*)(Al + ga);
            *(uint4*)&sBh[row * PADK + col] = *(const uint4*)(Bh + gbp);
            *(uint4*)&sBl[row * PADK + col] = *(const uint4*)(Bl + gbp);
        }
        __syncthreads();

#pragma unroll
        for (int ks2 = 0; ks2 < 2; ks2++) {
            const int ks = ks2 * 16;
            uint32_t ah[4][4], al[4][4];
#pragma unroll
            for (int mf = 0; mf < 4; mf++) {
                int arow = wm * 64 + mf * 16 + r + (g & 1) * 8;
                int acol = ks + (g >> 1) * 8;
                uint32_t off = (uint32_t)(arow * PADK + acol) * 2;
                LDSM4(ah[mf], uAh + off);
                LDSM4(al[mf], uAl + off);
            }
            uint32_t bh[8], bl[8];
#pragma unroll
            for (int np = 0; np < 2; np++) {
                int brow = wn * 32 + np * 16 + r + (g >> 1) * 8;
                int bcol = ks + (g & 1) * 8;
                uint32_t off = (uint32_t)(brow * PADK + bcol) * 2;
                LDSM4(&bh[np * 4], uBh + off);
                LDSM4(&bl[np * 4], uBl + off);
            }
#pragma unroll
            for (int mf = 0; mf < 4; mf++)
#pragma unroll
                for (int nf = 0; nf < 4; nf++) {
                    const uint32_t* bph = &bh[(nf >> 1) * 4 + (nf & 1) * 2];
                    const uint32_t* bpl = &bl[(nf >> 1) * 4 + (nf & 1) * 2];
                    mma16816(acc[mf][nf], ah[mf], bph);
                    mma16816(acc[mf][nf], ah[mf], bpl);
                    mma16816(acc[mf][nf], al[mf], bph);
                }
        }
        __syncthreads();
    }

    // epilogue
    const int mbase = by * 128 + wm * 64;
    const int nbase = bx * 128 + wn * 32;
#pragma unroll
    for (int mf = 0; mf < 4; mf++)
#pragma unroll
        for (int h2 = 0; h2 < 2; h2++) {
            int m = mbase + mf * 16 + (lane >> 2) + h2 * 8;
            float bs = bias[m];
#pragma unroll
            for (int nf = 0; nf < 4; nf++) {
                int n = nbase + nf * 8 + (lane & 3) * 2;
                float v0 = acc[mf][nf][h2 * 2]     + bs;
                float v1 = acc[mf][nf][h2 * 2 + 1] + bs;
                if (MODE == 0) {
                    if (m < CH) { v0 *= 0.125f; v1 *= 0.125f; }   // q scale
                    size_t o = ((size_t)bz * 3 * CH + m) * SEQ + n;
                    float h0, l0, h1, l1;
                    split2(v0, h0, l0); split2(v1, h1, l1);
                    *(uint32_t*)&Oh[o] = pk2(h0, h1);
                    *(uint32_t*)&Ol[o] = pk2(l0, l1);
                } else {
                    size_t o = ((size_t)bz * CH + m) * SEQ + n;
                    float2 xv = *(const float2*)&resid[o];
                    float2 ov; ov.x = v0 + xv.x; ov.y = v1 + xv.y;
                    *(float2*)&outf[o] = ov;
                }
            }
        }
}

// ---------------------------------------------------------------------------
// Kernel 3: flash attention on mma.sync. grid (16 i-tiles, 4 heads, 16 batch),
// 256 threads = 8 warps (2m x 4n). i-tile 64, j-tile 64, 16 j-iterations.
// smem tiles (bf16, rows padded to 72): Q/K/V [64d][64sj] hi+lo, P [64i][64j]
// hi+lo, plus fp32 reduction arrays.
// ---------------------------------------------------------------------------
#define TP 72                       // padded tile row (elems)
#define T_ELEM (64 * TP)            // 4608 elems per plane
#define OFF_QH 0
#define OFF_QL (1 * T_ELEM)
#define OFF_KH (2 * T_ELEM)
#define OFF_KL (3 * T_ELEM)
#define OFF_VH (4 * T_ELEM)
#define OFF_VL (5 * T_ELEM)
#define OFF_PH (6 * T_ELEM)
#define OFF_PL (7 * T_ELEM)
#define OFF_RED (8 * T_ELEM * 2)    // byte offset of fp32 arrays
#define ATT_SMEM (OFF_RED + 2048)   // + smax[256] + ssum[256]

__global__ __launch_bounds__(256)
void attn_kernel(const bf16* __restrict__ qh, const bf16* __restrict__ ql,
                 bf16* __restrict__ ah, bf16* __restrict__ al)
{
    extern __shared__ __align__(16) char smc[];
    unsigned short* st = (unsigned short*)smc;
    float* smax = (float*)(smc + OFF_RED);
    float* ssum = smax + 256;
    const uint32_t sb = smem_u32(smc);

    const int tid = threadIdx.x, lane = tid & 31, w = tid >> 5;
    const int wm = w >> 2, wn = w & 3;
    const int i0 = blockIdx.x * 64;
    const int hh = blockIdx.y;
    const int b  = blockIdx.z;
    const int r = lane & 7, g = lane >> 3;

    const size_t qrow0 = (size_t)b * 3 * CH + hh * 64;          // q channels
    const size_t krow0 = qrow0 + CH;
    const size_t vrow0 = qrow0 + 2 * CH;

    // stage Q tile [64d][64i] hi/lo
#pragma unroll
    for (int rr = 0; rr < 2; rr++) {
        int lin = tid * 8 + rr * 2048;
        int d = lin >> 6, col = lin & 63;
        *(uint4*)&st[OFF_QH + d * TP + col] =
            *(const uint4*)(qh + (qrow0 + d) * SEQ + i0 + col);
        *(uint4*)&st[OFF_QL + d * TP + col] =
            *(const uint4*)(ql + (qrow0 + d) * SEQ + i0 + col);
    }

    float oacc[2][2][4] = {};
    float mr[2][2] = {{-1e30f, -1e30f}, {-1e30f, -1e30f}};
    float lr[2][2] = {};

    for (int jt = 0; jt < 16; jt++) {
        const int j0 = jt * 64;
        __syncthreads();   // previous stage-2 done; safe to overwrite K/V
#pragma unroll
        for (int rr = 0; rr < 2; rr++) {
            int lin = tid * 8 + rr * 2048;
            int d = lin >> 6, col = lin & 63;
            *(uint4*)&st[OFF_KH + d * TP + col] =
                *(const uint4*)(qh + (krow0 + d) * SEQ + j0 + col);
            *(uint4*)&st[OFF_KL + d * TP + col] =
                *(const uint4*)(ql + (krow0 + d) * SEQ + j0 + col);
            *(uint4*)&st[OFF_VH + d * TP + col] =
                *(const uint4*)(qh + (vrow0 + d) * SEQ + j0 + col);
            *(uint4*)&st[OFF_VL + d * TP + col] =
                *(const uint4*)(ql + (vrow0 + d) * SEQ + j0 + col);
        }
        __syncthreads();

        // ---- stage 1: S = Q^T K  (warp: i 32 x j 16) ----
        float sacc[2][2][4] = {};
#pragma unroll
        for (int dk = 0; dk < 4; dk++) {
            uint32_t qa_h[2][4], qa_l[2][4];
#pragma unroll
            for (int mf = 0; mf < 2; mf++) {
                int qr = dk * 16 + r + (g >> 1) * 8;
                int qc = wm * 32 + mf * 16 + (g & 1) * 8;
                uint32_t offh = sb + (uint32_t)(OFF_QH + qr * TP + qc) * 2;
                uint32_t offl = sb + (uint32_t)(OFF_QL + qr * TP + qc) * 2;
                LDSM4T(qa_h[mf], offh);
                LDSM4T(qa_l[mf], offl);
            }
            uint32_t kb_h[4], kb_l[4];
            {
                int kr = dk * 16 + r + (g & 1) * 8;
                int kc2 = wn * 16 + (g >> 1) * 8;
                LDSM4T(kb_h, sb + (uint32_t)(OFF_KH + kr * TP + kc2) * 2);
                LDSM4T(kb_l, sb + (uint32_t)(OFF_KL + kr * TP + kc2) * 2);
            }
#pragma unroll
            for (int mf = 0; mf < 2; mf++)
#pragma unroll
                for (int nf = 0; nf < 2; nf++) {
                    mma16816(sacc[mf][nf], qa_h[mf], &kb_h[nf * 2]);
                    mma16816(sacc[mf][nf], qa_h[mf], &kb_l[nf * 2]);
                    mma16816(sacc[mf][nf], qa_l[mf], &kb_h[nf * 2]);
                }
        }

        // ---- online softmax ----
#pragma unroll
        for (int mf = 0; mf < 2; mf++)
#pragma unroll
            for (int h2 = 0; h2 < 2; h2++) {
                float vm = fmaxf(fmaxf(sacc[mf][0][h2*2], sacc[mf][0][h2*2+1]),
                                 fmaxf(sacc[mf][1][h2*2], sacc[mf][1][h2*2+1]));
                vm = fmaxf(vm, __shfl_xor_sync(0xffffffffu, vm, 1));
                vm = fmaxf(vm, __shfl_xor_sync(0xffffffffu, vm, 2));
                if ((lane & 3) == 0) {
                    int row = wm * 32 + mf * 16 + (lane >> 2) + h2 * 8;
                    smax[row * 4 + wn] = vm;
                }
            }
        __syncthreads();

        float corr[2][2];
#pragma unroll
        for (int mf = 0; mf < 2; mf++)
#pragma unroll
            for (int h2 = 0; h2 < 2; h2++) {
                int row = wm * 32 + mf * 16 + (lane >> 2) + h2 * 8;
                float gm = fmaxf(fmaxf(smax[row*4+0], smax[row*4+1]),
                                 fmaxf(smax[row*4+2], smax[row*4+3]));
                float nm = fmaxf(mr[mf][h2], gm);
                corr[mf][h2] = __expf(mr[mf][h2] - nm);
                mr[mf][h2] = nm;
                float qs = 0.f;
#pragma unroll
                for (int nf = 0; nf < 2; nf++)
#pragma unroll
                    for (int c = 0; c < 2; c++) {
                        float p = __expf(sacc[mf][nf][h2*2+c] - nm);
                        sacc[mf][nf][h2*2+c] = p;
                        qs += p;
                    }
                qs += __shfl_xor_sync(0xffffffffu, qs, 1);
                qs += __shfl_xor_sync(0xffffffffu, qs, 2);
                if ((lane & 3) == 0) ssum[row * 4 + wn] = qs;
#pragma unroll
                for (int nf = 0; nf < 2; nf++)
#pragma unroll
                    for (int c = 0; c < 2; c++)
                        oacc[mf][nf][h2*2+c] *= corr[mf][h2];
            }
        __syncthreads();

#pragma unroll
        for (int mf = 0; mf < 2; mf++)
#pragma unroll
            for (int h2 = 0; h2 < 2; h2++) {
                int row = wm * 32 + mf * 16 + (lane >> 2) + h2 * 8;
                float rs = ssum[row*4+0] + ssum[row*4+1]
                         + ssum[row*4+2] + ssum[row*4+3];
                lr[mf][h2] = lr[mf][h2] * corr[mf][h2] + rs;
#pragma unroll
                for (int nf = 0; nf < 2; nf++) {
                    int col = wn * 16 + nf * 8 + (lane & 3) * 2;
                    float p0 = sacc[mf][nf][h2*2], p1 = sacc[mf][nf][h2*2+1];
                    float h0, l0, h1, l1;
                    split2(p0, h0, l0); split2(p1, h1, l1);
                    *(uint32_t*)&st[OFF_PH + row * TP + col] = pk2(h0, h1);
                    *(uint32_t*)&st[OFF_PL + row * TP + col] = pk2(l0, l1);
                }
            }
        __syncthreads();

        // ---- stage 2: O += P V^T  (warp: i 32 x d 16) ----
#pragma unroll
        for (int jk = 0; jk < 4; jk++) {
            uint32_t pa_h[2][4], pa_l[2][4];
#pragma unroll
            for (int mf = 0; mf < 2; mf++) {
                int pr = wm * 32 + mf * 16 + r + (g & 1) * 8;
                int pc = jk * 16 + (g >> 1) * 8;
                LDSM4(pa_h[mf], sb + (uint32_t)(OFF_PH + pr * TP + pc) * 2);
                LDSM4(pa_l[mf], sb + (uint32_t)(OFF_PL + pr * TP + pc) * 2);
            }
            uint32_t vb_h[4], vb_l[4];
            {
                int vr = wn * 16 + r + (g >> 1) * 8;
                int vc = jk * 16 + (g & 1) * 8;
                LDSM4(vb_h, sb + (uint32_t)(OFF_VH + vr * TP + vc) * 2);
                LDSM4(vb_l, sb + (uint32_t)(OFF_VL + vr * TP + vc) * 2);
            }
#pragma unroll
            for (int mf = 0; mf < 2; mf++)
#pragma unroll
                for (int nf = 0; nf < 2; nf++) {
                    mma16816(oacc[mf][nf], pa_h[mf], &vb_h[nf * 2]);
                    mma16816(oacc[mf][nf], pa_h[mf], &vb_l[nf * 2]);
                    mma16816(oacc[mf][nf], pa_l[mf], &vb_h[nf * 2]);
                }
        }
    }

    // ---- epilogue: O/l -> split att planes [b][s][c], c = hh*64 + d ----
#pragma unroll
    for (int mf = 0; mf < 2; mf++)
#pragma unroll
        for (int h2 = 0; h2 < 2; h2++) {
            int row = wm * 32 + mf * 16 + (lane >> 2) + h2 * 8;
            int s = i0 + row;
            float inv = 1.0f / lr[mf][h2];
#pragma unroll
            for (int nf = 0; nf < 2; nf++) {
                int c = hh * 64 + wn * 16 + nf * 8 + (lane & 3) * 2;
                float v0 = oacc[mf][nf][h2*2]     * inv;
                float v1 = oacc[mf][nf][h2*2 + 1] * inv;
                float h0, l0, h1, l1;
                split2(v0, h0, l0); split2(v1, h1, l1);
                size_t o = ((size_t)b * SEQ + s) * CH + c;
                *(uint32_t*)&ah[o] = pk2(h0, h1);
                *(uint32_t*)&al[o] = pk2(l0, l1);
            }
        }
}

// ---------------------------------------------------------------------------
extern "C" void kernel_launch(void* const* d_in, const int* in_sizes, int n_in,
                              void* d_out, int out_size)
{
    const float* x      = (const float*)d_in[0];
    const float* gn_w   = (const float*)d_in[1];
    const float* gn_b   = (const float*)d_in[2];
    const float* qkv_w  = (const float*)d_in[3];
    const float* qkv_b  = (const float*)d_in[4];
    const float* proj_w = (const float*)d_in[5];
    const float* proj_b = (const float*)d_in[6];
    float* out = (float*)d_out;

    bf16 *qh, *ql, *yh, *yl, *ahp, *alp, *wqh, *wql, *wph, *wpl;
    cudaGetSymbolAddress((void**)&qh,  g_qh);
    cudaGetSymbolAddress((void**)&ql,  g_ql);
    cudaGetSymbolAddress((void**)&yh,  g_yh);
    cudaGetSymbolAddress((void**)&yl,  g_yl);
    cudaGetSymbolAddress((void**)&ahp, g_ah);
    cudaGetSymbolAddress((void**)&alp, g_al);
    cudaGetSymbolAddress((void**)&wqh, g_wqh);
    cudaGetSymbolAddress((void**)&wql, g_wql);
    cudaGetSymbolAddress((void**)&wph, g_wph);
    cudaGetSymbolAddress((void**)&wpl, g_wpl);

    cudaFuncSetAttribute(attn_kernel,
                         cudaFuncAttributeMaxDynamicSharedMemorySize, ATT_SMEM);

    // 0. split weights
    split_kernel<<<(3 * CH * CH + 255) / 256, 256>>>(qkv_w, wqh, wql, 3 * CH * CH);
    split_kernel<<<(CH * CH + 255) / 256, 256>>>(proj_w, wph, wpl, CH * CH);

    // 1. GroupNorm -> split y planes [b][s][c]
    gn_kernel<<<BATCH * GROUPS, 256>>>(x, gn_w, gn_b, yh, yl);

    // 2. qkv = Wqkv @ y + b (q pre-scaled) -> split planes [b][768][s]
    mma_gemm<0><<<dim3(SEQ / 128, 3 * CH / 128, BATCH), 256>>>(
        wqh, wql, yh, yl, qkv_b, nullptr, qh, ql, nullptr);

    // 3. flash attention (mma) -> split att planes [b][s][c]
    attn_kernel<<<dim3(SEQ / 64, HEADS, BATCH), 256, ATT_SMEM>>>(qh, ql, ahp, alp);

    // 4. out = x + Wproj @ att + b  (fp32 out)
    mma_gemm<1><<<dim3(SEQ / 128, CH / 128, BATCH), 256>>>(
        wph, wpl, ahp, alp, proj_b, x, nullptr, nullptr, out);
}

// round 6
// speedup vs baseline: 3.4205x; 1.1117x over previous
#include <cuda_runtime.h>
#include <cuda_bf16.h>
#include <math.h>
#include <cstdint>

// ---------------------------------------------------------------------------
// SelfAttention2d via warp-level mma.sync (bf16 split hi/lo, fp32 accum),
// now with cp.async double-buffered pipelines in all tensor kernels and
// SW128-swizzled attention tiles (2 CTAs/SM retained).
// ---------------------------------------------------------------------------

#define BATCH 16
#define CH    256
#define SEQ   1024
#define HEADS 4
#define GROUPS 32
#define CPG   8
#define GN_ELEMS 8192

typedef __nv_bfloat16 bf16;

// --------------------------- scratch (static) -------------------------------
__device__ __align__(256) bf16 g_qh[BATCH * 3 * CH * SEQ];  // qkv hi [b][768][s]
__device__ __align__(256) bf16 g_ql[BATCH * 3 * CH * SEQ];
__device__ __align__(256) bf16 g_yh[BATCH * SEQ * CH];      // gn out [b][s][c]
__device__ __align__(256) bf16 g_yl[BATCH * SEQ * CH];
__device__ __align__(256) bf16 g_ah[BATCH * SEQ * CH];      // attn out [b][s][c]
__device__ __align__(256) bf16 g_al[BATCH * SEQ * CH];
__device__ __align__(256) bf16 g_wqh[3 * CH * CH];
__device__ __align__(256) bf16 g_wql[3 * CH * CH];
__device__ __align__(256) bf16 g_wph[CH * CH];
__device__ __align__(256) bf16 g_wpl[CH * CH];

// --------------------------- helpers ----------------------------------------
__device__ __forceinline__ uint32_t smem_u32(const void* p) {
    uint32_t a;
    asm("{ .reg .u64 t; cvta.to.shared.u64 t, %1; cvt.u32.u64 %0, t; }"
        : "=r"(a) : "l"(p));
    return a;
}
__device__ __forceinline__ uint32_t swz(uint32_t b) {   // SW128 for 128B rows
    return b ^ ((b >> 3) & 0x70);
}

#define LDSM4(R, A)                                                          \
    asm volatile("ldmatrix.sync.aligned.m8n8.x4.shared.b16 {%0,%1,%2,%3},[%4];" \
        : "=r"((R)[0]), "=r"((R)[1]), "=r"((R)[2]), "=r"((R)[3]) : "r"(A))
#define LDSM4T(R, A)                                                         \
    asm volatile("ldmatrix.sync.aligned.m8n8.x4.trans.shared.b16 {%0,%1,%2,%3},[%4];" \
        : "=r"((R)[0]), "=r"((R)[1]), "=r"((R)[2]), "=r"((R)[3]) : "r"(A))

#define CP16(dst, src)                                                       \
    asm volatile("cp.async.cg.shared.global [%0], [%1], 16;"                 \
        :: "r"((uint32_t)(dst)), "l"(src))
#define CP_COMMIT() asm volatile("cp.async.commit_group;" ::: "memory")
#define CP_WAIT(n)  asm volatile("cp.async.wait_group %0;" :: "n"(n) : "memory")

__device__ __forceinline__ void mma16816(float* d, const uint32_t* a,
                                         const uint32_t* b) {
    asm volatile(
        "mma.sync.aligned.m16n8k16.row.col.f32.bf16.bf16.f32 "
        "{%0,%1,%2,%3}, {%4,%5,%6,%7}, {%8,%9}, {%0,%1,%2,%3};"
        : "+f"(d[0]), "+f"(d[1]), "+f"(d[2]), "+f"(d[3])
        : "r"(a[0]), "r"(a[1]), "r"(a[2]), "r"(a[3]), "r"(b[0]), "r"(b[1]));
}

__device__ __forceinline__ uint32_t pk2(float a, float b) {
    bf16 x = __float2bfloat16(a), y = __float2bfloat16(b);
    return (uint32_t)*(unsigned short*)&x | ((uint32_t)*(unsigned short*)&y << 16);
}
__device__ __forceinline__ void split2(float v, float& h, float& l) {
    bf16 hb = __float2bfloat16(v);
    h = __bfloat162float(hb);
    l = v - h;
}

// ---------------------------------------------------------------------------
// Kernel 0: fp32 -> (hi, lo) bf16 split of weights
// ---------------------------------------------------------------------------
__global__ void split_kernel(const float* __restrict__ w,
                             bf16* __restrict__ hi, bf16* __restrict__ lo, int n)
{
    int i = blockIdx.x * blockDim.x + threadIdx.x;
    if (i < n) {
        float v = w[i], h, l;
        split2(v, h, l);
        hi[i] = __float2bfloat16(h);
        lo[i] = __float2bfloat16(l);
    }
}

// ---------------------------------------------------------------------------
// Kernel 1: GroupNorm -> split-bf16 planes [b][s][c]. One block per (b,g).
// ---------------------------------------------------------------------------
#define BUFP 1028

__global__ __launch_bounds__(256)
void gn_kernel(const float* __restrict__ x,
               const float* __restrict__ gw,
               const float* __restrict__ gb,
               bf16* __restrict__ yh, bf16* __restrict__ yl)
{
    __shared__ float s1[256], s2[256];
    __shared__ float buf[CPG * BUFP];

    const int bg  = blockIdx.x;
    const int b   = bg >> 5;
    const int g   = bg & 31;
    const int tid = threadIdx.x;
    const float4* __restrict__ xp = (const float4*)(x + (size_t)bg * GN_ELEMS);

    float s = 0.f, ss = 0.f;
#pragma unroll
    for (int r = 0; r < 8; r++) {
        float4 v = xp[tid + r * 256];
        s  += v.x + v.y + v.z + v.w;
        ss += v.x*v.x + v.y*v.y + v.z*v.z + v.w*v.w;
        *(float4*)&buf[r * BUFP + tid * 4] = v;
    }
    s1[tid] = s; s2[tid] = ss;
    __syncthreads();
    for (int st = 128; st > 0; st >>= 1) {
        if (tid < st) { s1[tid] += s1[tid + st]; s2[tid] += s2[tid + st]; }
        __syncthreads();
    }
    const float mean = s1[0] * (1.0f / GN_ELEMS);
    const float var  = s2[0] * (1.0f / GN_ELEMS) - mean * mean;
    const float inv  = rsqrtf(var + 1e-5f);

    float wsc[CPG], bia[CPG];
#pragma unroll
    for (int cc = 0; cc < CPG; cc++) {
        wsc[cc] = gw[g * CPG + cc] * inv;
        bia[cc] = gb[g * CPG + cc] - mean * wsc[cc];
    }

    union { uint32_t u[4]; uint4 v; } ph, pl;
#pragma unroll
    for (int q = 0; q < 4; q++) {
        int sp = tid + q * 256;
        size_t o = ((size_t)b * SEQ + sp) * CH + g * CPG;
#pragma unroll
        for (int p2 = 0; p2 < 4; p2++) {
            float v0 = buf[(p2*2    ) * BUFP + sp] * wsc[p2*2    ] + bia[p2*2    ];
            float v1 = buf[(p2*2 + 1) * BUFP + sp] * wsc[p2*2 + 1] + bia[p2*2 + 1];
            float h0, l0, h1, l1;
            split2(v0, h0, l0); split2(v1, h1, l1);
            ph.u[p2] = pk2(h0, h1);
            pl.u[p2] = pk2(l0, l1);
        }
        *(uint4*)&yh[o] = ph.v;
        *(uint4*)&yl[o] = pl.v;
    }
}

// ---------------------------------------------------------------------------
// Kernel 2/4: split-bf16 mma GEMM, cp.async double-buffered.
// D[m][n] = sum_k A[m][k]*B[n][k]; block 128x128, 8 warps (2m x 4n), k=32.
// MODE 0: qkv -> split bf16 planes [b][m][SEQ], q rows scaled by 0.125.
// MODE 1: proj -> fp32 out + bias + residual.
// ---------------------------------------------------------------------------
#define PADK 40
#define GP   (128 * PADK)          // plane elems (5120)
#define GBUF (4 * GP)              // buffer elems
#define GSM_BYTES (2 * GBUF * 2)   // 81920 bytes

template <int MODE>
__global__ __launch_bounds__(256)
void mma_gemm(const bf16* __restrict__ Ah, const bf16* __restrict__ Al,
              const bf16* __restrict__ Bh, const bf16* __restrict__ Bl,
              const float* __restrict__ bias, const float* __restrict__ resid,
              bf16* __restrict__ Oh, bf16* __restrict__ Ol,
              float* __restrict__ outf)
{
    extern __shared__ __align__(16) unsigned short smg[];
    const uint32_t sb0 = smem_u32(smg);

    const int tid = threadIdx.x, lane = tid & 31, w = tid >> 5;
    const int wm = w >> 2, wn = w & 3;
    const int bx = blockIdx.x, by = blockIdx.y, bz = blockIdx.z;

    const size_t abase = (size_t)by * 128 * 256;
    const size_t bbase = ((size_t)bz * SEQ + bx * 128) * 256;

    const int lrow = tid >> 2;            // 0..63
    const int lcol = (tid & 3) * 8;       // 0..24

    float acc[4][4][4] = {};
    const int r = lane & 7, g = lane >> 3;

    // prologue: chunk 0 -> buffer 0
#pragma unroll
    for (int rr = 0; rr < 2; rr++) {
        int row = lrow + rr * 64;
        uint32_t doff = (uint32_t)(row * PADK + lcol) * 2;
        size_t ga = abase + (size_t)row * 256 + lcol;
        size_t gb = bbase + (size_t)row * 256 + lcol;
        CP16(sb0 + 0 * GP * 2 + doff, Ah + ga);
        CP16(sb0 + 1 * GP * 2 + doff, Al + ga);
        CP16(sb0 + 2 * GP * 2 + doff, Bh + gb);
        CP16(sb0 + 3 * GP * 2 + doff, Bl + gb);
    }
    CP_COMMIT();

    for (int kc = 0; kc < 8; kc++) {
        if (kc < 7) {
            const int k0 = (kc + 1) * 32;
            const uint32_t d = sb0 + ((kc + 1) & 1) * (GBUF * 2);
#pragma unroll
            for (int rr = 0; rr < 2; rr++) {
                int row = lrow + rr * 64;
                uint32_t doff = (uint32_t)(row * PADK + lcol) * 2;
                size_t ga = abase + (size_t)row * 256 + k0 + lcol;
                size_t gb = bbase + (size_t)row * 256 + k0 + lcol;
                CP16(d + 0 * GP * 2 + doff, Ah + ga);
                CP16(d + 1 * GP * 2 + doff, Al + ga);
                CP16(d + 2 * GP * 2 + doff, Bh + gb);
                CP16(d + 3 * GP * 2 + doff, Bl + gb);
            }
            CP_COMMIT();
            CP_WAIT(1);
        } else {
            CP_WAIT(0);
        }
        __syncthreads();

        const uint32_t ub  = sb0 + (kc & 1) * (GBUF * 2);
        const uint32_t uAh = ub,              uAl = ub + GP * 2;
        const uint32_t uBh = ub + 2 * GP * 2, uBl = ub + 3 * GP * 2;

#pragma unroll
        for (int ks2 = 0; ks2 < 2; ks2++) {
            const int ks = ks2 * 16;
            uint32_t ah[4][4], al[4][4];
#pragma unroll
            for (int mf = 0; mf < 4; mf++) {
                int arow = wm * 64 + mf * 16 + r + (g & 1) * 8;
                int acol = ks + (g >> 1) * 8;
                uint32_t off = (uint32_t)(arow * PADK + acol) * 2;
                LDSM4(ah[mf], uAh + off);
                LDSM4(al[mf], uAl + off);
            }
            uint32_t bh[8], bl[8];
#pragma unroll
            for (int np = 0; np < 2; np++) {
                int brow = wn * 32 + np * 16 + r + (g >> 1) * 8;
                int bcol = ks + (g & 1) * 8;
                uint32_t off = (uint32_t)(brow * PADK + bcol) * 2;
                LDSM4(&bh[np * 4], uBh + off);
                LDSM4(&bl[np * 4], uBl + off);
            }
#pragma unroll
            for (int mf = 0; mf < 4; mf++)
#pragma unroll
                for (int nf = 0; nf < 4; nf++) {
                    const uint32_t* bph = &bh[(nf >> 1) * 4 + (nf & 1) * 2];
                    const uint32_t* bpl = &bl[(nf >> 1) * 4 + (nf & 1) * 2];
                    mma16816(acc[mf][nf], ah[mf], bph);
                    mma16816(acc[mf][nf], ah[mf], bpl);
                    mma16816(acc[mf][nf], al[mf], bph);
                }
        }
        __syncthreads();
    }

    // epilogue
    const int mbase = by * 128 + wm * 64;
    const int nbase = bx * 128 + wn * 32;
#pragma unroll
    for (int mf = 0; mf < 4; mf++)
#pragma unroll
        for (int h2 = 0; h2 < 2; h2++) {
            int m = mbase + mf * 16 + (lane >> 2) + h2 * 8;
            float bs = bias[m];
#pragma unroll
            for (int nf = 0; nf < 4; nf++) {
                int n = nbase + nf * 8 + (lane & 3) * 2;
                float v0 = acc[mf][nf][h2 * 2]     + bs;
                float v1 = acc[mf][nf][h2 * 2 + 1] + bs;
                if (MODE == 0) {
                    if (m < CH) { v0 *= 0.125f; v1 *= 0.125f; }   // q scale
                    size_t o = ((size_t)bz * 3 * CH + m) * SEQ + n;
                    float h0, l0, h1, l1;
                    split2(v0, h0, l0); split2(v1, h1, l1);
                    *(uint32_t*)&Oh[o] = pk2(h0, h1);
                    *(uint32_t*)&Ol[o] = pk2(l0, l1);
                } else {
                    size_t o = ((size_t)bz * CH + m) * SEQ + n;
                    float2 xv = *(const float2*)&resid[o];
                    float2 ov; ov.x = v0 + xv.x; ov.y = v1 + xv.y;
                    *(float2*)&outf[o] = ov;
                }
            }
        }
}

// ---------------------------------------------------------------------------
// Kernel 3: flash attention on mma.sync, SW128-swizzled tiles, double-buffered
// cp.async K/V prefetch. grid (16, 4, 16), 256 threads = 8 warps (2m x 4n).
// planes (8192B each): QH QL | KV buf0 {KH KL VH VL} | KV buf1 | PH PL | red.
// ---------------------------------------------------------------------------
#define PB 8192
#define OQH 0
#define OQL PB
#define OKV(b) (2 * PB + (b) * (4 * PB))
#define OPH (10 * PB)
#define OPL (11 * PB)
#define ORED (12 * PB)
#define ATT_SMEM (ORED + 2048)

__global__ __launch_bounds__(256)
void attn_kernel(const bf16* __restrict__ qh, const bf16* __restrict__ ql,
                 bf16* __restrict__ ah, bf16* __restrict__ al)
{
    extern __shared__ __align__(16) char smc[];
    float* smax = (float*)(smc + ORED);
    float* ssum = smax + 256;
    const uint32_t sb = smem_u32(smc);

    const int tid = threadIdx.x, lane = tid & 31, w = tid >> 5;
    const int wm = w >> 2, wn = w & 3;
    const int i0 = blockIdx.x * 64;
    const int hh = blockIdx.y;
    const int b  = blockIdx.z;
    const int r = lane & 7, g = lane >> 3;

    const size_t qrow0 = (size_t)b * 3 * CH + hh * 64;
    const size_t krow0 = qrow0 + CH;
    const size_t vrow0 = qrow0 + 2 * CH;

    const int ld_d = tid >> 3;        // 0..31 ; rr adds 32
    const int ld_c = (tid & 7) * 8;   // col 0..56

    // prologue: Q + KV(jt=0)
#pragma unroll
    for (int rr = 0; rr < 2; rr++) {
        int d = ld_d + rr * 32;
        uint32_t doff = swz((uint32_t)(d * 128 + ld_c * 2));
        size_t qi = (qrow0 + d) * SEQ + i0 + ld_c;
        CP16(sb + OQH + doff, qh + qi);
        CP16(sb + OQL + doff, ql + qi);
        size_t ki = (krow0 + d) * SEQ + ld_c;
        size_t vi = (vrow0 + d) * SEQ + ld_c;
        uint32_t kb = sb + OKV(0) + doff;
        CP16(kb,          qh + ki);
        CP16(kb + PB,     ql + ki);
        CP16(kb + 2 * PB, qh + vi);
        CP16(kb + 3 * PB, ql + vi);
    }
    CP_COMMIT();

    float oacc[2][2][4] = {};
    float mr[2][2] = {{-1e30f, -1e30f}, {-1e30f, -1e30f}};
    float lr[2][2] = {};

    for (int jt = 0; jt < 16; jt++) {
        __syncthreads();   // previous stage-2 complete everywhere
        if (jt < 15) {
            const int j0 = (jt + 1) * 64;
            const uint32_t kb0 = sb + OKV((jt + 1) & 1);
#pragma unroll
            for (int rr = 0; rr < 2; rr++) {
                int d = ld_d + rr * 32;
                uint32_t doff = swz((uint32_t)(d * 128 + ld_c * 2));
                size_t ki = (krow0 + d) * SEQ + j0 + ld_c;
                size_t vi = (vrow0 + d) * SEQ + j0 + ld_c;
                CP16(kb0 + doff,          qh + ki);
                CP16(kb0 + PB + doff,     ql + ki);
                CP16(kb0 + 2 * PB + doff, qh + vi);
                CP16(kb0 + 3 * PB + doff, ql + vi);
            }
            CP_COMMIT();
            CP_WAIT(1);
        } else {
            CP_WAIT(0);
        }
        __syncthreads();

        const uint32_t kvb = sb + OKV(jt & 1);

        // ---- stage 1: S = Q^T K  (warp: i 32 x j 16) ----
        float sacc[2][2][4] = {};
#pragma unroll
        for (int dk = 0; dk < 4; dk++) {
            uint32_t qa_h[2][4], qa_l[2][4];
#pragma unroll
            for (int mf = 0; mf < 2; mf++) {
                int qr = dk * 16 + r + (g >> 1) * 8;
                int qc = wm * 32 + mf * 16 + (g & 1) * 8;
                uint32_t o2 = swz((uint32_t)(qr * 128 + qc * 2));
                LDSM4T(qa_h[mf], sb + OQH + o2);
                LDSM4T(qa_l[mf], sb + OQL + o2);
            }
            uint32_t kb_h[4], kb_l[4];
            {
                int kr = dk * 16 + r + (g & 1) * 8;
                int kc2 = wn * 16 + (g >> 1) * 8;
                uint32_t o2 = swz((uint32_t)(kr * 128 + kc2 * 2));
                LDSM4T(kb_h, kvb + o2);
                LDSM4T(kb_l, kvb + PB + o2);
            }
#pragma unroll
            for (int mf = 0; mf < 2; mf++)
#pragma unroll
                for (int nf = 0; nf < 2; nf++) {
                    mma16816(sacc[mf][nf], qa_h[mf], &kb_h[nf * 2]);
                    mma16816(sacc[mf][nf], qa_h[mf], &kb_l[nf * 2]);
                    mma16816(sacc[mf][nf], qa_l[mf], &kb_h[nf * 2]);
                }
        }

        // ---- online softmax ----
#pragma unroll
        for (int mf = 0; mf < 2; mf++)
#pragma unroll
            for (int h2 = 0; h2 < 2; h2++) {
                float vm = fmaxf(fmaxf(sacc[mf][0][h2*2], sacc[mf][0][h2*2+1]),
                                 fmaxf(sacc[mf][1][h2*2], sacc[mf][1][h2*2+1]));
                vm = fmaxf(vm, __shfl_xor_sync(0xffffffffu, vm, 1));
                vm = fmaxf(vm, __shfl_xor_sync(0xffffffffu, vm, 2));
                if ((lane & 3) == 0) {
                    int row = wm * 32 + mf * 16 + (lane >> 2) + h2 * 8;
                    smax[row * 4 + wn] = vm;
                }
            }
        __syncthreads();

        float corr[2][2];
#pragma unroll
        for (int mf = 0; mf < 2; mf++)
#pragma unroll
            for (int h2 = 0; h2 < 2; h2++) {
                int row = wm * 32 + mf * 16 + (lane >> 2) + h2 * 8;
                float gm = fmaxf(fmaxf(smax[row*4+0], smax[row*4+1]),
                                 fmaxf(smax[row*4+2], smax[row*4+3]));
                float nm = fmaxf(mr[mf][h2], gm);
                corr[mf][h2] = __expf(mr[mf][h2] - nm);
                mr[mf][h2] = nm;
                float qs = 0.f;
#pragma unroll
                for (int nf = 0; nf < 2; nf++)
#pragma unroll
                    for (int c = 0; c < 2; c++) {
                        float p = __expf(sacc[mf][nf][h2*2+c] - nm);
                        sacc[mf][nf][h2*2+c] = p;
                        qs += p;
                    }
                qs += __shfl_xor_sync(0xffffffffu, qs, 1);
                qs += __shfl_xor_sync(0xffffffffu, qs, 2);
                if ((lane & 3) == 0) ssum[row * 4 + wn] = qs;
#pragma unroll
                for (int nf = 0; nf < 2; nf++)
#pragma unroll
                    for (int c = 0; c < 2; c++)
                        oacc[mf][nf][h2*2+c] *= corr[mf][h2];
            }
        __syncthreads();

#pragma unroll
        for (int mf = 0; mf < 2; mf++)
#pragma unroll
            for (int h2 = 0; h2 < 2; h2++) {
                int row = wm * 32 + mf * 16 + (lane >> 2) + h2 * 8;
                float rs = ssum[row*4+0] + ssum[row*4+1]
                         + ssum[row*4+2] + ssum[row*4+3];
                lr[mf][h2] = lr[mf][h2] * corr[mf][h2] + rs;
#pragma unroll
                for (int nf = 0; nf < 2; nf++) {
                    int col = wn * 16 + nf * 8 + (lane & 3) * 2;
                    float p0 = sacc[mf][nf][h2*2], p1 = sacc[mf][nf][h2*2+1];
                    float h0, l0, h1, l1;
                    split2(p0, h0, l0); split2(p1, h1, l1);
                    uint32_t o2 = swz((uint32_t)(row * 128 + col * 2));
                    *(uint32_t*)(smc + OPH + o2) = pk2(h0, h1);
                    *(uint32_t*)(smc + OPL + o2) = pk2(l0, l1);
                }
            }
        __syncthreads();

        // ---- stage 2: O += P V^T  (warp: i 32 x d 16) ----
#pragma unroll
        for (int jk = 0; jk < 4; jk++) {
            uint32_t pa_h[2][4], pa_l[2][4];
#pragma unroll
            for (int mf = 0; mf < 2; mf++) {
                int pr = wm * 32 + mf * 16 + r + (g & 1) * 8;
                int pc = jk * 16 + (g >> 1) * 8;
                uint32_t o2 = swz((uint32_t)(pr * 128 + pc * 2));
                LDSM4(pa_h[mf], sb + OPH + o2);
                LDSM4(pa_l[mf], sb + OPL + o2);
            }
            uint32_t vb_h[4], vb_l[4];
            {
                int vr = wn * 16 + r + (g >> 1) * 8;
                int vc = jk * 16 + (g & 1) * 8;
                uint32_t o2 = swz((uint32_t)(vr * 128 + vc * 2));
                LDSM4(vb_h, kvb + 2 * PB + o2);
                LDSM4(vb_l, kvb + 3 * PB + o2);
            }
#pragma unroll
            for (int mf = 0; mf < 2; mf++)
#pragma unroll
                for (int nf = 0; nf < 2; nf++) {
                    mma16816(oacc[mf][nf], pa_h[mf], &vb_h[nf * 2]);
                    mma16816(oacc[mf][nf], pa_h[mf], &vb_l[nf * 2]);
                    mma16816(oacc[mf][nf], pa_l[mf], &vb_h[nf * 2]);
                }
        }
    }

    // ---- epilogue: O/l -> split att planes [b][s][c] ----
#pragma unroll
    for (int mf = 0; mf < 2; mf++)
#pragma unroll
        for (int h2 = 0; h2 < 2; h2++) {
            int row = wm * 32 + mf * 16 + (lane >> 2) + h2 * 8;
            int s = i0 + row;
            float inv = 1.0f / lr[mf][h2];
#pragma unroll
            for (int nf = 0; nf < 2; nf++) {
                int c = hh * 64 + wn * 16 + nf * 8 + (lane & 3) * 2;
                float v0 = oacc[mf][nf][h2*2]     * inv;
                float v1 = oacc[mf][nf][h2*2 + 1] * inv;
                float h0, l0, h1, l1;
                split2(v0, h0, l0); split2(v1, h1, l1);
                size_t o = ((size_t)b * SEQ + s) * CH + c;
                *(uint32_t*)&ah[o] = pk2(h0, h1);
                *(uint32_t*)&al[o] = pk2(l0, l1);
            }
        }
}

// ---------------------------------------------------------------------------
extern "C" void kernel_launch(void* const* d_in, const int* in_sizes, int n_in,
                              void* d_out, int out_size)
{
    const float* x      = (const float*)d_in[0];
    const float* gn_w   = (const float*)d_in[1];
    const float* gn_b   = (const float*)d_in[2];
    const float* qkv_w  = (const float*)d_in[3];
    const float* qkv_b  = (const float*)d_in[4];
    const float* proj_w = (const float*)d_in[5];
    const float* proj_b = (const float*)d_in[6];
    float* out = (float*)d_out;

    bf16 *qh, *ql, *yh, *yl, *ahp, *alp, *wqh, *wql, *wph, *wpl;
    cudaGetSymbolAddress((void**)&qh,  g_qh);
    cudaGetSymbolAddress((void**)&ql,  g_ql);
    cudaGetSymbolAddress((void**)&yh,  g_yh);
    cudaGetSymbolAddress((void**)&yl,  g_yl);
    cudaGetSymbolAddress((void**)&ahp, g_ah);
    cudaGetSymbolAddress((void**)&alp, g_al);
    cudaGetSymbolAddress((void**)&wqh, g_wqh);
    cudaGetSymbolAddress((void**)&wql, g_wql);
    cudaGetSymbolAddress((void**)&wph, g_wph);
    cudaGetSymbolAddress((void**)&wpl, g_wpl);

    cudaFuncSetAttribute(mma_gemm<0>,
                         cudaFuncAttributeMaxDynamicSharedMemorySize, GSM_BYTES);
    cudaFuncSetAttribute(mma_gemm<1>,
                         cudaFuncAttributeMaxDynamicSharedMemorySize, GSM_BYTES);
    cudaFuncSetAttribute(attn_kernel,
                         cudaFuncAttributeMaxDynamicSharedMemorySize, ATT_SMEM);

    // 0. split weights
    split_kernel<<<(3 * CH * CH + 255) / 256, 256>>>(qkv_w, wqh, wql, 3 * CH * CH);
    split_kernel<<<(CH * CH + 255) / 256, 256>>>(proj_w, wph, wpl, CH * CH);

    // 1. GroupNorm -> split y planes [b][s][c]
    gn_kernel<<<BATCH * GROUPS, 256>>>(x, gn_w, gn_b, yh, yl);

    // 2. qkv = Wqkv @ y + b (q pre-scaled) -> split planes [b][768][s]
    mma_gemm<0><<<dim3(SEQ / 128, 3 * CH / 128, BATCH), 256, GSM_BYTES>>>(
        wqh, wql, yh, yl, qkv_b, nullptr, qh, ql, nullptr);

    // 3. flash attention (mma) -> split att planes [b][s][c]
    attn_kernel<<<dim3(SEQ / 64, HEADS, BATCH), 256, ATT_SMEM>>>(qh, ql, ahp, alp);

    // 4. out = x + Wproj @ att + b  (fp32 out)
    mma_gemm<1><<<dim3(SEQ / 128, CH / 128, BATCH), 256, GSM_BYTES>>>(
        wph, wpl, ahp, alp, proj_b, x, nullptr, nullptr, out);
}

// round 7
// speedup vs baseline: 4.2352x; 1.2382x over previous
#include <cuda_runtime.h>
#include <cuda_fp16.h>
#include <math.h>
#include <cstdint>

// ---------------------------------------------------------------------------
// SelfAttention2d via mma.sync fp16 split (hi/lo weights x single-fp16
// activations, fp32 accum). 2 MMAs/logical-MAC in GEMMs and PV, 3 in QK.
// cp.async double-buffered pipelines, SW128-swizzled attention tiles.
// ---------------------------------------------------------------------------

#define BATCH 16
#define CH    256
#define SEQ   1024
#define HEADS 4
#define GROUPS 32
#define CPG   8
#define GN_ELEMS 8192

typedef __half fp16;

// --------------------------- scratch (static) -------------------------------
__device__ __align__(256) fp16 g_qh[BATCH * 3 * CH * SEQ];  // qkv hi [b][768][s]
__device__ __align__(256) fp16 g_ql[BATCH * 3 * CH * SEQ];  // qkv lo
__device__ __align__(256) fp16 g_y [BATCH * SEQ * CH];      // gn out [b][s][c]
__device__ __align__(256) fp16 g_a [BATCH * SEQ * CH];      // attn out [b][s][c]
__device__ __align__(256) fp16 g_wqh[3 * CH * CH];
__device__ __align__(256) fp16 g_wql[3 * CH * CH];
__device__ __align__(256) fp16 g_wph[CH * CH];
__device__ __align__(256) fp16 g_wpl[CH * CH];

// --------------------------- helpers ----------------------------------------
__device__ __forceinline__ uint32_t smem_u32(const void* p) {
    uint32_t a;
    asm("{ .reg .u64 t; cvta.to.shared.u64 t, %1; cvt.u32.u64 %0, t; }"
        : "=r"(a) : "l"(p));
    return a;
}
__device__ __forceinline__ uint32_t swz(uint32_t b) {   // SW128 for 128B rows
    return b ^ ((b >> 3) & 0x70);
}

#define LDSM4(R, A)                                                          \
    asm volatile("ldmatrix.sync.aligned.m8n8.x4.shared.b16 {%0,%1,%2,%3},[%4];" \
        : "=r"((R)[0]), "=r"((R)[1]), "=r"((R)[2]), "=r"((R)[3]) : "r"(A))
#define LDSM4T(R, A)                                                         \
    asm volatile("ldmatrix.sync.aligned.m8n8.x4.trans.shared.b16 {%0,%1,%2,%3},[%4];" \
        : "=r"((R)[0]), "=r"((R)[1]), "=r"((R)[2]), "=r"((R)[3]) : "r"(A))

#define CP16(dst, src)                                                       \
    asm volatile("cp.async.cg.shared.global [%0], [%1], 16;"                 \
        :: "r"((uint32_t)(dst)), "l"(src))
#define CP_COMMIT() asm volatile("cp.async.commit_group;" ::: "memory")
#define CP_WAIT(n)  asm volatile("cp.async.wait_group %0;" :: "n"(n) : "memory")

__device__ __forceinline__ void mma16816(float* d, const uint32_t* a,
                                         const uint32_t* b) {
    asm volatile(
        "mma.sync.aligned.m16n8k16.row.col.f32.f16.f16.f32 "
        "{%0,%1,%2,%3}, {%4,%5,%6,%7}, {%8,%9}, {%0,%1,%2,%3};"
        : "+f"(d[0]), "+f"(d[1]), "+f"(d[2]), "+f"(d[3])
        : "r"(a[0]), "r"(a[1]), "r"(a[2]), "r"(a[3]), "r"(b[0]), "r"(b[1]));
}

__device__ __forceinline__ uint32_t pk2(float a, float b) {
    fp16 x = __float2half_rn(a), y = __float2half_rn(b);
    return (uint32_t)*(unsigned short*)&x | ((uint32_t)*(unsigned short*)&y << 16);
}
__device__ __forceinline__ void split2(float v, float& h, float& l) {
    fp16 hb = __float2half_rn(v);
    h = __half2float(hb);
    l = v - h;
}

// ---------------------------------------------------------------------------
// Kernel 0: fp32 -> (hi, lo) fp16 split of weights
// ---------------------------------------------------------------------------
__global__ void split_kernel(const float* __restrict__ w,
                             fp16* __restrict__ hi, fp16* __restrict__ lo, int n)
{
    int i = blockIdx.x * blockDim.x + threadIdx.x;
    if (i < n) {
        float v = w[i], h, l;
        split2(v, h, l);
        hi[i] = __float2half_rn(h);
        lo[i] = __float2half_rn(l);
    }
}

// ---------------------------------------------------------------------------
// Kernel 1: GroupNorm -> single fp16 plane [b][s][c]. One block per (b,g).
// ---------------------------------------------------------------------------
#define BUFP 1028

__global__ __launch_bounds__(256)
void gn_kernel(const float* __restrict__ x,
               const float* __restrict__ gw,
               const float* __restrict__ gb,
               fp16* __restrict__ y)
{
    __shared__ float s1[256], s2[256];
    __shared__ float buf[CPG * BUFP];

    const int bg  = blockIdx.x;
    const int b   = bg >> 5;
    const int g   = bg & 31;
    const int tid = threadIdx.x;
    const float4* __restrict__ xp = (const float4*)(x + (size_t)bg * GN_ELEMS);

    float s = 0.f, ss = 0.f;
#pragma unroll
    for (int r = 0; r < 8; r++) {
        float4 v = xp[tid + r * 256];
        s  += v.x + v.y + v.z + v.w;
        ss += v.x*v.x + v.y*v.y + v.z*v.z + v.w*v.w;
        *(float4*)&buf[r * BUFP + tid * 4] = v;
    }
    s1[tid] = s; s2[tid] = ss;
    __syncthreads();
    for (int st = 128; st > 0; st >>= 1) {
        if (tid < st) { s1[tid] += s1[tid + st]; s2[tid] += s2[tid + st]; }
        __syncthreads();
    }
    const float mean = s1[0] * (1.0f / GN_ELEMS);
    const float var  = s2[0] * (1.0f / GN_ELEMS) - mean * mean;
    const float inv  = rsqrtf(var + 1e-5f);

    float wsc[CPG], bia[CPG];
#pragma unroll
    for (int cc = 0; cc < CPG; cc++) {
        wsc[cc] = gw[g * CPG + cc] * inv;
        bia[cc] = gb[g * CPG + cc] - mean * wsc[cc];
    }

    union { uint32_t u[4]; uint4 v; } ph;
#pragma unroll
    for (int q = 0; q < 4; q++) {
        int sp = tid + q * 256;
        size_t o = ((size_t)b * SEQ + sp) * CH + g * CPG;
#pragma unroll
        for (int p2 = 0; p2 < 4; p2++) {
            float v0 = buf[(p2*2    ) * BUFP + sp] * wsc[p2*2    ] + bia[p2*2    ];
            float v1 = buf[(p2*2 + 1) * BUFP + sp] * wsc[p2*2 + 1] + bia[p2*2 + 1];
            ph.u[p2] = pk2(v0, v1);
        }
        *(uint4*)&y[o] = ph.v;
    }
}

// ---------------------------------------------------------------------------
// Kernel 2/4: 2-term fp16 mma GEMM, cp.async double-buffered.
// D[m][n] = sum_k (Wh+Wl)[m][k]*B[n][k]; block 128x128, 8 warps, k=32.
// MODE 0: qkv -> fp16 hi/lo planes [b][m][SEQ], q rows scaled by 0.125.
// MODE 1: proj -> fp32 out + bias + residual.
// ---------------------------------------------------------------------------
#define PADK 40
#define GP   (128 * PADK)          // plane elems (5120)
#define GBUF (3 * GP)              // buffer elems (Wh, Wl, B)
#define GSM_BYTES (2 * GBUF * 2)   // 61440 bytes

template <int MODE>
__global__ __launch_bounds__(256)
void mma_gemm(const fp16* __restrict__ Ah, const fp16* __restrict__ Al,
              const fp16* __restrict__ Bs,
              const float* __restrict__ bias, const float* __restrict__ resid,
              fp16* __restrict__ Oh, fp16* __restrict__ Ol,
              float* __restrict__ outf)
{
    extern __shared__ __align__(16) unsigned short smg[];
    const uint32_t sb0 = smem_u32(smg);

    const int tid = threadIdx.x, lane = tid & 31, w = tid >> 5;
    const int wm = w >> 2, wn = w & 3;
    const int bx = blockIdx.x, by = blockIdx.y, bz = blockIdx.z;

    const size_t abase = (size_t)by * 128 * 256;
    const size_t bbase = ((size_t)bz * SEQ + bx * 128) * 256;

    const int lrow = tid >> 2;            // 0..63
    const int lcol = (tid & 3) * 8;       // 0..24

    float acc[4][4][4] = {};
    const int r = lane & 7, g = lane >> 3;

    // prologue: chunk 0 -> buffer 0
#pragma unroll
    for (int rr = 0; rr < 2; rr++) {
        int row = lrow + rr * 64;
        uint32_t doff = (uint32_t)(row * PADK + lcol) * 2;
        size_t ga = abase + (size_t)row * 256 + lcol;
        size_t gb = bbase + (size_t)row * 256 + lcol;
        CP16(sb0 + 0 * GP * 2 + doff, Ah + ga);
        CP16(sb0 + 1 * GP * 2 + doff, Al + ga);
        CP16(sb0 + 2 * GP * 2 + doff, Bs + gb);
    }
    CP_COMMIT();

    for (int kc = 0; kc < 8; kc++) {
        if (kc < 7) {
            const int k0 = (kc + 1) * 32;
            const uint32_t d = sb0 + ((kc + 1) & 1) * (GBUF * 2);
#pragma unroll
            for (int rr = 0; rr < 2; rr++) {
                int row = lrow + rr * 64;
                uint32_t doff = (uint32_t)(row * PADK + lcol) * 2;
                size_t ga = abase + (size_t)row * 256 + k0 + lcol;
                size_t gb = bbase + (size_t)row * 256 + k0 + lcol;
                CP16(d + 0 * GP * 2 + doff, Ah + ga);
                CP16(d + 1 * GP * 2 + doff, Al + ga);
                CP16(d + 2 * GP * 2 + doff, Bs + gb);
            }
            CP_COMMIT();
            CP_WAIT(1);
        } else {
            CP_WAIT(0);
        }
        __syncthreads();

        const uint32_t ub  = sb0 + (kc & 1) * (GBUF * 2);
        const uint32_t uAh = ub, uAl = ub + GP * 2, uB = ub + 2 * GP * 2;

#pragma unroll
        for (int ks2 = 0; ks2 < 2; ks2++) {
            const int ks = ks2 * 16;
            uint32_t ah[4][4], al[4][4];
#pragma unroll
            for (int mf = 0; mf < 4; mf++) {
                int arow = wm * 64 + mf * 16 + r + (g & 1) * 8;
                int acol = ks + (g >> 1) * 8;
                uint32_t off = (uint32_t)(arow * PADK + acol) * 2;
                LDSM4(ah[mf], uAh + off);
                LDSM4(al[mf], uAl + off);
            }
            uint32_t bh[8];
#pragma unroll
            for (int np = 0; np < 2; np++) {
                int brow = wn * 32 + np * 16 + r + (g >> 1) * 8;
                int bcol = ks + (g & 1) * 8;
                uint32_t off = (uint32_t)(brow * PADK + bcol) * 2;
                LDSM4(&bh[np * 4], uB + off);
            }
#pragma unroll
            for (int mf = 0; mf < 4; mf++)
#pragma unroll
                for (int nf = 0; nf < 4; nf++) {
                    const uint32_t* bp = &bh[(nf >> 1) * 4 + (nf & 1) * 2];
                    mma16816(acc[mf][nf], ah[mf], bp);
                    mma16816(acc[mf][nf], al[mf], bp);
                }
        }
        __syncthreads();
    }

    // epilogue
    const int mbase = by * 128 + wm * 64;
    const int nbase = bx * 128 + wn * 32;
#pragma unroll
    for (int mf = 0; mf < 4; mf++)
#pragma unroll
        for (int h2 = 0; h2 < 2; h2++) {
            int m = mbase + mf * 16 + (lane >> 2) + h2 * 8;
            float bs = bias[m];
#pragma unroll
            for (int nf = 0; nf < 4; nf++) {
                int n = nbase + nf * 8 + (lane & 3) * 2;
                float v0 = acc[mf][nf][h2 * 2]     + bs;
                float v1 = acc[mf][nf][h2 * 2 + 1] + bs;
                if (MODE == 0) {
                    if (m < CH) { v0 *= 0.125f; v1 *= 0.125f; }   // q scale
                    size_t o = ((size_t)bz * 3 * CH + m) * SEQ + n;
                    float h0, l0, h1, l1;
                    split2(v0, h0, l0); split2(v1, h1, l1);
                    *(uint32_t*)&Oh[o] = pk2(h0, h1);
                    *(uint32_t*)&Ol[o] = pk2(l0, l1);
                } else {
                    size_t o = ((size_t)bz * CH + m) * SEQ + n;
                    float2 xv = *(const float2*)&resid[o];
                    float2 ov; ov.x = v0 + xv.x; ov.y = v1 + xv.y;
                    *(float2*)&outf[o] = ov;
                }
            }
        }
}

// ---------------------------------------------------------------------------
// Kernel 3: flash attention. QK: q,k hi/lo 3-term. PV: P single fp16, V hi/lo
// 2-term. SW128 tiles, double-buffered cp.async K/V. 256 thr = 8 warps.
// planes (8192B): QH QL | KV0 {KH KL VH VL} | KV1 | P | red
// ---------------------------------------------------------------------------
#define PB 8192
#define OQH 0
#define OQL PB
#define OKV(b) (2 * PB + (b) * (4 * PB))
#define OP  (10 * PB)
#define ORED (11 * PB)
#define ATT_SMEM (ORED + 2048)

__global__ __launch_bounds__(256)
void attn_kernel(const fp16* __restrict__ qh, const fp16* __restrict__ ql,
                 fp16* __restrict__ ao)
{
    extern __shared__ __align__(16) char smc[];
    float* smax = (float*)(smc + ORED);
    float* ssum = smax + 256;
    const uint32_t sb = smem_u32(smc);

    const int tid = threadIdx.x, lane = tid & 31, w = tid >> 5;
    const int wm = w >> 2, wn = w & 3;
    const int i0 = blockIdx.x * 64;
    const int hh = blockIdx.y;
    const int b  = blockIdx.z;
    const int r = lane & 7, g = lane >> 3;

    const size_t qrow0 = (size_t)b * 3 * CH + hh * 64;
    const size_t krow0 = qrow0 + CH;
    const size_t vrow0 = qrow0 + 2 * CH;

    const int ld_d = tid >> 3;        // 0..31 ; rr adds 32
    const int ld_c = (tid & 7) * 8;   // col 0..56

    // prologue: Q + KV(jt=0)
#pragma unroll
    for (int rr = 0; rr < 2; rr++) {
        int d = ld_d + rr * 32;
        uint32_t doff = swz((uint32_t)(d * 128 + ld_c * 2));
        size_t qi = (qrow0 + d) * SEQ + i0 + ld_c;
        CP16(sb + OQH + doff, qh + qi);
        CP16(sb + OQL + doff, ql + qi);
        size_t ki = (krow0 + d) * SEQ + ld_c;
        size_t vi = (vrow0 + d) * SEQ + ld_c;
        uint32_t kb = sb + OKV(0) + doff;
        CP16(kb,          qh + ki);
        CP16(kb + PB,     ql + ki);
        CP16(kb + 2 * PB, qh + vi);
        CP16(kb + 3 * PB, ql + vi);
    }
    CP_COMMIT();

    float oacc[2][2][4] = {};
    float mr[2][2] = {{-1e30f, -1e30f}, {-1e30f, -1e30f}};
    float lr[2][2] = {};

    for (int jt = 0; jt < 16; jt++) {
        __syncthreads();   // previous stage-2 complete everywhere
        if (jt < 15) {
            const int j0 = (jt + 1) * 64;
            const uint32_t kb0 = sb + OKV((jt + 1) & 1);
#pragma unroll
            for (int rr = 0; rr < 2; rr++) {
                int d = ld_d + rr * 32;
                uint32_t doff = swz((uint32_t)(d * 128 + ld_c * 2));
                size_t ki = (krow0 + d) * SEQ + j0 + ld_c;
                size_t vi = (vrow0 + d) * SEQ + j0 + ld_c;
                CP16(kb0 + doff,          qh + ki);
                CP16(kb0 + PB + doff,     ql + ki);
                CP16(kb0 + 2 * PB + doff, qh + vi);
                CP16(kb0 + 3 * PB + doff, ql + vi);
            }
            CP_COMMIT();
            CP_WAIT(1);
        } else {
            CP_WAIT(0);
        }
        __syncthreads();

        const uint32_t kvb = sb + OKV(jt & 1);

        // ---- stage 1: S = Q^T K  (warp: i 32 x j 16), 3-term ----
        float sacc[2][2][4] = {};
#pragma unroll
        for (int dk = 0; dk < 4; dk++) {
            uint32_t qa_h[2][4], qa_l[2][4];
#pragma unroll
            for (int mf = 0; mf < 2; mf++) {
                int qr = dk * 16 + r + (g >> 1) * 8;
                int qc = wm * 32 + mf * 16 + (g & 1) * 8;
                uint32_t o2 = swz((uint32_t)(qr * 128 + qc * 2));
                LDSM4T(qa_h[mf], sb + OQH + o2);
                LDSM4T(qa_l[mf], sb + OQL + o2);
            }
            uint32_t kb_h[4], kb_l[4];
            {
                int kr = dk * 16 + r + (g & 1) * 8;
                int kc2 = wn * 16 + (g >> 1) * 8;
                uint32_t o2 = swz((uint32_t)(kr * 128 + kc2 * 2));
                LDSM4T(kb_h, kvb + o2);
                LDSM4T(kb_l, kvb + PB + o2);
            }
#pragma unroll
            for (int mf = 0; mf < 2; mf++)
#pragma unroll
                for (int nf = 0; nf < 2; nf++) {
                    mma16816(sacc[mf][nf], qa_h[mf], &kb_h[nf * 2]);
                    mma16816(sacc[mf][nf], qa_h[mf], &kb_l[nf * 2]);
                    mma16816(sacc[mf][nf], qa_l[mf], &kb_h[nf * 2]);
                }
        }

        // ---- online softmax ----
#pragma unroll
        for (int mf = 0; mf < 2; mf++)
#pragma unroll
            for (int h2 = 0; h2 < 2; h2++) {
                float vm = fmaxf(fmaxf(sacc[mf][0][h2*2], sacc[mf][0][h2*2+1]),
                                 fmaxf(sacc[mf][1][h2*2], sacc[mf][1][h2*2+1]));
                vm = fmaxf(vm, __shfl_xor_sync(0xffffffffu, vm, 1));
                vm = fmaxf(vm, __shfl_xor_sync(0xffffffffu, vm, 2));
                if ((lane & 3) == 0) {
                    int row = wm * 32 + mf * 16 + (lane >> 2) + h2 * 8;
                    smax[row * 4 + wn] = vm;
                }
            }
        __syncthreads();

        float corr[2][2];
#pragma unroll
        for (int mf = 0; mf < 2; mf++)
#pragma unroll
            for (int h2 = 0; h2 < 2; h2++) {
                int row = wm * 32 + mf * 16 + (lane >> 2) + h2 * 8;
                float gm = fmaxf(fmaxf(smax[row*4+0], smax[row*4+1]),
                                 fmaxf(smax[row*4+2], smax[row*4+3]));
                float nm = fmaxf(mr[mf][h2], gm);
                corr[mf][h2] = __expf(mr[mf][h2] - nm);
                mr[mf][h2] = nm;
                float qs = 0.f;
#pragma unroll
                for (int nf = 0; nf < 2; nf++)
#pragma unroll
                    for (int c = 0; c < 2; c++) {
                        float p = __expf(sacc[mf][nf][h2*2+c] - nm);
                        sacc[mf][nf][h2*2+c] = p;
                        qs += p;
                    }
                qs += __shfl_xor_sync(0xffffffffu, qs, 1);
                qs += __shfl_xor_sync(0xffffffffu, qs, 2);
                if ((lane & 3) == 0) ssum[row * 4 + wn] = qs;
#pragma unroll
                for (int nf = 0; nf < 2; nf++)
#pragma unroll
                    for (int c = 0; c < 2; c++)
                        oacc[mf][nf][h2*2+c] *= corr[mf][h2];
            }
        __syncthreads();

#pragma unroll
        for (int mf = 0; mf < 2; mf++)
#pragma unroll
            for (int h2 = 0; h2 < 2; h2++) {
                int row = wm * 32 + mf * 16 + (lane >> 2) + h2 * 8;
                float rs = ssum[row*4+0] + ssum[row*4+1]
                         + ssum[row*4+2] + ssum[row*4+3];
                lr[mf][h2] = lr[mf][h2] * corr[mf][h2] + rs;
#pragma unroll
                for (int nf = 0; nf < 2; nf++) {
                    int col = wn * 16 + nf * 8 + (lane & 3) * 2;
                    uint32_t o2 = swz((uint32_t)(row * 128 + col * 2));
                    *(uint32_t*)(smc + OP + o2) =
                        pk2(sacc[mf][nf][h2*2], sacc[mf][nf][h2*2+1]);
                }
            }
        __syncthreads();

        // ---- stage 2: O += P V^T  (warp: i 32 x d 16), 2-term ----
#pragma unroll
        for (int jk = 0; jk < 4; jk++) {
            uint32_t pa[2][4];
#pragma unroll
            for (int mf = 0; mf < 2; mf++) {
                int pr = wm * 32 + mf * 16 + r + (g & 1) * 8;
                int pc = jk * 16 + (g >> 1) * 8;
                uint32_t o2 = swz((uint32_t)(pr * 128 + pc * 2));
                LDSM4(pa[mf], sb + OP + o2);
            }
            uint32_t vb_h[4], vb_l[4];
            {
                int vr = wn * 16 + r + (g >> 1) * 8;
                int vc = jk * 16 + (g & 1) * 8;
                uint32_t o2 = swz((uint32_t)(vr * 128 + vc * 2));
                LDSM4(vb_h, kvb + 2 * PB + o2);
                LDSM4(vb_l, kvb + 3 * PB + o2);
            }
#pragma unroll
            for (int mf = 0; mf < 2; mf++)
#pragma unroll
                for (int nf = 0; nf < 2; nf++) {
                    mma16816(oacc[mf][nf], pa[mf], &vb_h[nf * 2]);
                    mma16816(oacc[mf][nf], pa[mf], &vb_l[nf * 2]);
                }
        }
    }

    // ---- epilogue: O/l -> single fp16 att plane [b][s][c] ----
#pragma unroll
    for (int mf = 0; mf < 2; mf++)
#pragma unroll
        for (int h2 = 0; h2 < 2; h2++) {
            int row = wm * 32 + mf * 16 + (lane >> 2) + h2 * 8;
            int s = i0 + row;
            float inv = 1.0f / lr[mf][h2];
#pragma unroll
            for (int nf = 0; nf < 2; nf++) {
                int c = hh * 64 + wn * 16 + nf * 8 + (lane & 3) * 2;
                size_t o = ((size_t)b * SEQ + s) * CH + c;
                *(uint32_t*)&ao[o] = pk2(oacc[mf][nf][h2*2] * inv,
                                         oacc[mf][nf][h2*2 + 1] * inv);
            }
        }
}

// ---------------------------------------------------------------------------
extern "C" void kernel_launch(void* const* d_in, const int* in_sizes, int n_in,
                              void* d_out, int out_size)
{
    const float* x      = (const float*)d_in[0];
    const float* gn_w   = (const float*)d_in[1];
    const float* gn_b   = (const float*)d_in[2];
    const float* qkv_w  = (const float*)d_in[3];
    const float* qkv_b  = (const float*)d_in[4];
    const float* proj_w = (const float*)d_in[5];
    const float* proj_b = (const float*)d_in[6];
    float* out = (float*)d_out;

    fp16 *qh, *ql, *y, *a, *wqh, *wql, *wph, *wpl;
    cudaGetSymbolAddress((void**)&qh,  g_qh);
    cudaGetSymbolAddress((void**)&ql,  g_ql);
    cudaGetSymbolAddress((void**)&y,   g_y);
    cudaGetSymbolAddress((void**)&a,   g_a);
    cudaGetSymbolAddress((void**)&wqh, g_wqh);
    cudaGetSymbolAddress((void**)&wql, g_wql);
    cudaGetSymbolAddress((void**)&wph, g_wph);
    cudaGetSymbolAddress((void**)&wpl, g_wpl);

    cudaFuncSetAttribute(mma_gemm<0>,
                         cudaFuncAttributeMaxDynamicSharedMemorySize, GSM_BYTES);
    cudaFuncSetAttribute(mma_gemm<1>,
                         cudaFuncAttributeMaxDynamicSharedMemorySize, GSM_BYTES);
    cudaFuncSetAttribute(attn_kernel,
                         cudaFuncAttributeMaxDynamicSharedMemorySize, ATT_SMEM);

    // 0. split weights
    split_kernel<<<(3 * CH * CH + 255) / 256, 256>>>(qkv_w, wqh, wql, 3 * CH * CH);
    split_kernel<<<(CH * CH + 255) / 256, 256>>>(proj_w, wph, wpl, CH * CH);

    // 1. GroupNorm -> fp16 plane [b][s][c]
    gn_kernel<<<BATCH * GROUPS, 256>>>(x, gn_w, gn_b, y);

    // 2. qkv = (Wh+Wl) @ y + b (q pre-scaled) -> fp16 hi/lo [b][768][s]
    mma_gemm<0><<<dim3(SEQ / 128, 3 * CH / 128, BATCH), 256, GSM_BYTES>>>(
        wqh, wql, y, qkv_b, nullptr, qh, ql, nullptr);

    // 3. flash attention -> fp16 att plane [b][s][c]
    attn_kernel<<<dim3(SEQ / 64, HEADS, BATCH), 256, ATT_SMEM>>>(qh, ql, a);

    // 4. out = x + (Wh+Wl) @ att + b  (fp32 out)
    mma_gemm<1><<<dim3(SEQ / 128, CH / 128, BATCH), 256, GSM_BYTES>>>(
        wph, wpl, a, proj_b, x, nullptr, nullptr, out);
}